// round 7
// baseline (speedup 1.0000x reference)
#include <cuda_runtime.h>
#include <math.h>

#define EPSF 1e-5f

// ---------------- small scratch (no allocs allowed) ----------------
__device__ float g_diag[16 * 512 * 64];   // (n,t,h)   2 MB
__device__ float g_Wt2[576 * 64];         // W_tcn transposed: [(o'*9+k)][o]  147 KB
__device__ int   g_eraw[16 * 512];        // decoded edges, flattened (n,2,e)  32 KB

// ---------------- kernel 0: dtype-robust edge decode (int32 OR int64) --------
// Reads the buffer as int32 words. int64 layout => odd words (high halves of
// values in [0,64)) are all zero. int32 layout => odd words are uniform values
// in [0,64); P(all zero) ~ 64^-4096. Detection is data-driven, no metadata.
__global__ void edge_decode_kernel(const int* __restrict__ raw) {
    int tid = threadIdx.x;                 // 1024 threads, 1 block
    int acc = 0;
    for (int i = tid; i < 4096; i += 1024) acc |= raw[2 * i + 1];  // stays < 8192 words
    int any_odd = __syncthreads_or(acc != 0);
    bool is64 = (any_odd == 0);
    for (int i = tid; i < 8192; i += 1024)
        g_eraw[i] = is64 ? raw[2 * i] : raw[i];
}

// ---------------- kernel 1: transpose W_tcn -> [(o'*9+k)][o] ----------------
__global__ void wt_kernel(const float* __restrict__ W) {   // W[o][o'][k][1]
    int idx = blockIdx.x * blockDim.x + threadIdx.x;
    if (idx >= 64 * 576) return;
    int o = idx / 576, r = idx % 576;
    g_Wt2[r * 64 + o] = W[idx];
}

// ---------------- kernel 2: attention diag (edge-scan, atomic-free) ----------
// block = one (n,t); 64 threads (one per h)
__global__ void diag_kernel(const float* __restrict__ X,
                            const float* __restrict__ w1, const float* __restrict__ b1p,
                            const float* __restrict__ w2, const float* __restrict__ b2p) {
    int nt = blockIdx.x;          // 0..8191
    int n = nt >> 9;
    int h = threadIdx.x;

    __shared__ float sa1[64], sw1[64], sw2[64];
    __shared__ int   se[256];     // packed edges r*64+c for this n
    sw1[h] = w1[h];
    sw2[h] = w2[h];
    const int* ep = g_eraw + n * 512;   // (2,256) decoded int32
#pragma unroll
    for (int i = 0; i < 4; i++) {
        int e = h + i * 64;
        se[e] = ep[e] * 64 + ep[256 + e];
    }
    __syncthreads();

    const float4* xp = (const float4*)(X + ((size_t)nt * 64 + h) * 64);
    float d1 = 0.f, d2 = 0.f;
#pragma unroll
    for (int c4 = 0; c4 < 16; c4++) {
        float4 x = xp[c4];
        d1 += x.x * sw1[c4 * 4 + 0] + x.y * sw1[c4 * 4 + 1]
            + x.z * sw1[c4 * 4 + 2] + x.w * sw1[c4 * 4 + 3];
        d2 += x.x * sw2[c4 * 4 + 0] + x.y * sw2[c4 * 4 + 1]
            + x.z * sw2[c4 * 4 + 2] + x.w * sw2[c4 * 4 + 3];
    }
    sa1[h] = d1 + b1p[0];
    float a2h = d2 + b2p[0];
    __syncthreads();

    // denominator: softmax over k of lrelu(a1[k] + a2[h])
    float den = 0.f;
#pragma unroll 8
    for (int k = 0; k < 64; k++) {
        float v = sa1[k] + a2h;
        v = (v > 0.f) ? v : 0.01f * v;
        den += __expf(v);
    }
    // numerator: sum over edges (r==h): exp(lrelu(a1[c] + a2[h])), duplicates sum
    float num = 0.f;
    for (int i = 0; i < 256; i++) {
        int rc = se[i];
        if ((rc >> 6) == h) {
            float v = sa1[rc & 63] + a2h;
            v = (v > 0.f) ? v : 0.01f * v;
            num += __expf(v);
        }
    }
    g_diag[(size_t)nt * 64 + h] = num / den + 1.f;
}

// ---------------- kernel 3: FUSED support GEMM + bn1 + relu + temporal conv
//                  + bias + bn2 + residual + relu ----------------
// block: one (n,h) x a tile of 64 t's. 256 threads = 64 o x 4 t-groups.
__global__ void __launch_bounds__(256, 4)
fused_kernel(const float* __restrict__ X,
             const float* __restrict__ Wl, const float* __restrict__ bl,
             const float* __restrict__ g1, const float* __restrict__ be1,
             const float* __restrict__ bt,
             const float* __restrict__ g2, const float* __restrict__ be2,
             float* __restrict__ out) {
    __shared__ float buf[72][64];     // X tile, then reused as y1 tile
    __shared__ float Ws[64 * 65];     // W_lin transposed+padded: Ws[c*65+o]

    int bid = blockIdx.x;             // 0..8191
    int tb = bid & 7;
    int nh = bid >> 3;
    int n = nh >> 6, h = nh & 63;
    int t0 = tb * 64;
    int tid = threadIdx.x;

#pragma unroll
    for (int i = 0; i < 16; i++) {
        int idx = tid + i * 256;      // 4096 = 64*64
        int o = idx >> 6, c = idx & 63;
        Ws[c * 65 + o] = Wl[idx];
    }
#pragma unroll
    for (int i = 0; i < 18; i++) {
        int idx = tid + i * 256;      // 4608 = 72*64
        int r = idx >> 6, c = idx & 63;
        int t = t0 + r - 4;
        buf[r][c] = (t >= 0 && t < 512)
                  ? X[(((size_t)n * 512 + t) * 64 + h) * 64 + c] : 0.f;
    }
    __syncthreads();

    // --- phase 1: support GEMM + diag scale + bn1 + relu (into registers) ---
    int o = tid & 63;
    int tg = tid >> 6;                // 0..3
    float inv1 = g1[o] * rsqrtf(1.f + EPSF);
    float be1o = be1[o];
    float blo  = bl[o];
    float yreg[18];
#pragma unroll
    for (int j = 0; j < 18; j++) {
        int r = tg + 4 * j;           // covers 0..71
        float acc = 0.f;
#pragma unroll
        for (int c = 0; c < 64; c++) acc += buf[r][c] * Ws[c * 65 + o];
        int t = t0 + r - 4;
        float yv = 0.f;
        if (t >= 0 && t < 512) {
            float d = g_diag[((size_t)n * 512 + t) * 64 + h];
            yv = fmaxf(d * (acc + blo) * inv1 + be1o, 0.f);
        }
        yreg[j] = yv;                 // conv zero-padding for OOB rows
    }
    __syncthreads();
#pragma unroll
    for (int j = 0; j < 18; j++) buf[tg + 4 * j][o] = yreg[j];
    __syncthreads();

    // --- phase 2: temporal conv (K=9) over the 72-row y1 tile ---
    int tl = tg * 16;
    float acc[16];
#pragma unroll
    for (int i = 0; i < 16; i++) acc[i] = 0.f;

    for (int op = 0; op < 64; op++) {
        float v[24];
#pragma unroll
        for (int j = 0; j < 24; j++) v[j] = buf[tl + j][op];  // warp-broadcast LDS
        const float* wr = g_Wt2 + op * 9 * 64 + o;            // coalesced over lanes
#pragma unroll
        for (int k = 0; k < 9; k++) {
            float w = wr[k * 64];
#pragma unroll
            for (int i = 0; i < 16; i++) acc[i] += w * v[i + k];
        }
    }

    float inv2 = g2[o] * rsqrtf(1.f + EPSF);
    float bet2 = be2[o] + bt[o] * inv2;
    size_t base = (((size_t)n * 512 + t0 + tl) * 64 + h) * 64 + o;
#pragma unroll
    for (int i = 0; i < 16; i++) {
        size_t idx = base + (size_t)i * 64 * 64;   // +1 in t
        float val = acc[i] * inv2 + bet2 + X[idx]; // residual = X[n,t,h,o]
        out[idx] = fmaxf(val, 0.f);
    }
}

// ---------------- launch ----------------
extern "C" void kernel_launch(void* const* d_in, const int* in_sizes, int n_in,
                              void* d_out, int out_size) {
    const float* X     = (const float*)d_in[0];
    const int*   eraw  = (const int*)d_in[1];     // int32 OR int64 words; decoded on-device
    const float* w1    = (const float*)d_in[2];
    const float* b1    = (const float*)d_in[3];
    const float* w2    = (const float*)d_in[4];
    const float* b2    = (const float*)d_in[5];
    const float* Wl    = (const float*)d_in[6];
    const float* bl    = (const float*)d_in[7];
    const float* bn1g  = (const float*)d_in[8];
    const float* bn1b  = (const float*)d_in[9];
    const float* Wtcn  = (const float*)d_in[10];
    const float* btcn  = (const float*)d_in[11];
    const float* bn2g  = (const float*)d_in[12];
    const float* bn2b  = (const float*)d_in[13];
    float* out = (float*)d_out;

    edge_decode_kernel<<<1, 1024>>>(eraw);
    wt_kernel<<<(64 * 576 + 255) / 256, 256>>>(Wtcn);
    diag_kernel<<<16 * 512, 64>>>(X, w1, b1, w2, b2);
    fused_kernel<<<16 * 64 * 8, 256>>>(X, Wl, bl, bn1g, bn1b,
                                       btcn, bn2g, bn2b, out);
}

// round 8
// speedup vs baseline: 1.1460x; 1.1460x over previous
#include <cuda_runtime.h>
#include <math.h>

#define EPSF 1e-5f

// ---------------- small scratch (no allocs allowed) ----------------
__device__ float  g_diag[16 * 512 * 64];   // (n,t,h)  2 MB
__device__ float4 g_Wt4[64 * 3 * 64];      // packed conv weights [(op*3+q)*64+o] = {k=4q..4q+3}
__device__ int    g_eraw[16 * 512];        // decoded edges, flattened (n,2,e)  32 KB

// ---------------- kernel 0: dtype-robust edge decode (int32 OR int64) --------
__global__ void edge_decode_kernel(const int* __restrict__ raw) {
    int tid = threadIdx.x;                 // 1024 threads, 1 block
    int acc = 0;
    for (int i = tid; i < 4096; i += 1024) acc |= raw[2 * i + 1];
    int any_odd = __syncthreads_or(acc != 0);
    bool is64 = (any_odd == 0);
    for (int i = tid; i < 8192; i += 1024)
        g_eraw[i] = is64 ? raw[2 * i] : raw[i];
}

// ---------------- kernel 1: pack W_tcn -> float4 [(op*3+q)][o] ---------------
__global__ void wt_kernel(const float* __restrict__ W) {   // W[o][o'][k][1]
    int idx = blockIdx.x * blockDim.x + threadIdx.x;       // 64*3*64
    if (idx >= 64 * 3 * 64) return;
    int o = idx & 63;
    int t = idx >> 6;
    int q = t % 3, op = t / 3;
    float4 v;
    const float* wr = W + (size_t)o * 576 + op * 9;
    int k0 = 4 * q;
    v.x = (k0 + 0 < 9) ? wr[k0 + 0] : 0.f;
    v.y = (k0 + 1 < 9) ? wr[k0 + 1] : 0.f;
    v.z = (k0 + 2 < 9) ? wr[k0 + 2] : 0.f;
    v.w = (k0 + 3 < 9) ? wr[k0 + 3] : 0.f;
    g_Wt4[idx] = v;
}

// ---------------- kernel 2: attention diag (edge-scan, atomic-free) ----------
// block = one (n,t); 64 threads (one per h)
__global__ void diag_kernel(const float* __restrict__ X,
                            const float* __restrict__ w1, const float* __restrict__ b1p,
                            const float* __restrict__ w2, const float* __restrict__ b2p) {
    int nt = blockIdx.x;          // 0..8191
    int n = nt >> 9;
    int h = threadIdx.x;

    __shared__ float sa1[64], sw1[64], sw2[64];
    __shared__ int   se[256];
    sw1[h] = w1[h];
    sw2[h] = w2[h];
    const int* ep = g_eraw + n * 512;
#pragma unroll
    for (int i = 0; i < 4; i++) {
        int e = h + i * 64;
        se[e] = ep[e] * 64 + ep[256 + e];
    }
    __syncthreads();

    const float4* xp = (const float4*)(X + ((size_t)nt * 64 + h) * 64);
    float d1 = 0.f, d2 = 0.f;
#pragma unroll
    for (int c4 = 0; c4 < 16; c4++) {
        float4 x = xp[c4];
        d1 += x.x * sw1[c4 * 4 + 0] + x.y * sw1[c4 * 4 + 1]
            + x.z * sw1[c4 * 4 + 2] + x.w * sw1[c4 * 4 + 3];
        d2 += x.x * sw2[c4 * 4 + 0] + x.y * sw2[c4 * 4 + 1]
            + x.z * sw2[c4 * 4 + 2] + x.w * sw2[c4 * 4 + 3];
    }
    sa1[h] = d1 + b1p[0];
    float a2h = d2 + b2p[0];
    __syncthreads();

    float den = 0.f;
#pragma unroll 8
    for (int k = 0; k < 64; k++) {
        float v = sa1[k] + a2h;
        v = (v > 0.f) ? v : 0.01f * v;
        den += __expf(v);
    }
    float num = 0.f;
    for (int i = 0; i < 256; i++) {
        int rc = se[i];
        if ((rc >> 6) == h) {
            float v = sa1[rc & 63] + a2h;
            v = (v > 0.f) ? v : 0.01f * v;
            num += __expf(v);
        }
    }
    g_diag[(size_t)nt * 64 + h] = num / den + 1.f;
}

// ---------------- kernel 3: FUSED support GEMM + bn1 + relu + temporal conv
//                  + bias + bn2 + residual + relu ----------------
// block: one (n,h) x a tile of 64 t's. 256 threads = 64 o x 4 t-groups.
// bufs: first holds X tile [72 rows][64 ch] (r-major), then reused as the y1
// tile TRANSPOSED [64 ch][72 rows] (o-major) for vectorized conv reads.
__global__ void __launch_bounds__(256, 4)
fused_kernel(const float* __restrict__ X,
             const float* __restrict__ Wl, const float* __restrict__ bl,
             const float* __restrict__ g1, const float* __restrict__ be1,
             const float* __restrict__ bt,
             const float* __restrict__ g2, const float* __restrict__ be2,
             float* __restrict__ out) {
    __shared__ float bufs[72 * 64];
    __shared__ float Ws[64 * 65];     // W_lin transposed+padded: Ws[c*65+o]

    int bid = blockIdx.x;             // 0..8191
    int tb = bid & 7;
    int nh = bid >> 3;
    int n = nh >> 6, h = nh & 63;
    int t0 = tb * 64;
    int tid = threadIdx.x;

#pragma unroll
    for (int i = 0; i < 16; i++) {
        int idx = tid + i * 256;      // 4096 = 64*64
        int o = idx >> 6, c = idx & 63;
        Ws[c * 65 + o] = Wl[idx];
    }
    // X tile, float4-wide: 72 rows x 16 float4
    for (int q = tid; q < 72 * 16; q += 256) {
        int r = q >> 4, c4 = q & 15;
        int t = t0 + r - 4;
        float4 v = make_float4(0.f, 0.f, 0.f, 0.f);
        if (t >= 0 && t < 512)
            v = *(const float4*)(X + ((((size_t)n * 512 + t) * 64 + h) << 6) + c4 * 4);
        *(float4*)(bufs + r * 64 + c4 * 4) = v;
    }
    __syncthreads();

    // --- phase 1: support GEMM + diag scale + bn1 + relu (into registers) ---
    int o = tid & 63;
    int tg = tid >> 6;                // 0..3
    float acc1[18];
#pragma unroll
    for (int j = 0; j < 18; j++) acc1[j] = 0.f;
#pragma unroll
    for (int c4 = 0; c4 < 16; c4++) {
        float w0 = Ws[(4 * c4 + 0) * 65 + o];
        float w1 = Ws[(4 * c4 + 1) * 65 + o];
        float w2 = Ws[(4 * c4 + 2) * 65 + o];
        float w3 = Ws[(4 * c4 + 3) * 65 + o];
#pragma unroll
        for (int j = 0; j < 18; j++) {
            float4 x = *(const float4*)(bufs + (tg + 4 * j) * 64 + c4 * 4);
            acc1[j] += x.x * w0 + x.y * w1 + x.z * w2 + x.w * w3;
        }
    }

    float inv1 = g1[o] * rsqrtf(1.f + EPSF);
    float be1o = be1[o];
    float blo  = bl[o];
    float yreg[18];
#pragma unroll
    for (int j = 0; j < 18; j++) {
        int r = tg + 4 * j;           // covers 0..71
        int t = t0 + r - 4;
        float yv = 0.f;
        if (t >= 0 && t < 512) {
            float d = g_diag[((size_t)n * 512 + t) * 64 + h];
            yv = fmaxf(d * (acc1[j] + blo) * inv1 + be1o, 0.f);
        }
        yreg[j] = yv;                 // conv zero-padding for OOB rows
    }
    __syncthreads();
    // write y1 TRANSPOSED: bufs[o][r], row length 72 (72*64 = same footprint)
#pragma unroll
    for (int j = 0; j < 18; j++) bufs[o * 72 + tg + 4 * j] = yreg[j];
    __syncthreads();

    // --- phase 2: temporal conv (K=9) over the transposed y1 tile ---
    int tl = tg * 16;
    float acc[16];
#pragma unroll
    for (int i = 0; i < 16; i++) acc[i] = 0.f;

    for (int op = 0; op < 64; op++) {
        float v[24];
        const float4* vp = (const float4*)(bufs + op * 72 + tl);  // 16B-aligned
        float4* vv = (float4*)v;
#pragma unroll
        for (int q = 0; q < 6; q++) vv[q] = vp[q];                // broadcast LDS.128
        const float4* wp = g_Wt4 + op * 3 * 64 + o;               // coalesced LDG.128
        float4 wa = wp[0];        // k 0..3
        float4 wb = wp[64];       // k 4..7
        float4 wc = wp[128];      // k 8 (+pad)
#pragma unroll
        for (int i = 0; i < 16; i++) {
            acc[i] += wa.x * v[i + 0] + wa.y * v[i + 1]
                    + wa.z * v[i + 2] + wa.w * v[i + 3]
                    + wb.x * v[i + 4] + wb.y * v[i + 5]
                    + wb.z * v[i + 6] + wb.w * v[i + 7]
                    + wc.x * v[i + 8];
        }
    }

    float inv2 = g2[o] * rsqrtf(1.f + EPSF);
    float bet2 = be2[o] + bt[o] * inv2;
    size_t base = (((size_t)n * 512 + t0 + tl) * 64 + h) * 64 + o;
#pragma unroll
    for (int i = 0; i < 16; i++) {
        size_t idx = base + (size_t)i * 64 * 64;   // +1 in t
        float val = acc[i] * inv2 + bet2 + X[idx]; // residual = X[n,t,h,o]
        out[idx] = fmaxf(val, 0.f);
    }
}

// ---------------- launch ----------------
extern "C" void kernel_launch(void* const* d_in, const int* in_sizes, int n_in,
                              void* d_out, int out_size) {
    const float* X     = (const float*)d_in[0];
    const int*   eraw  = (const int*)d_in[1];     // int32 OR int64 words; decoded on-device
    const float* w1    = (const float*)d_in[2];
    const float* b1    = (const float*)d_in[3];
    const float* w2    = (const float*)d_in[4];
    const float* b2    = (const float*)d_in[5];
    const float* Wl    = (const float*)d_in[6];
    const float* bl    = (const float*)d_in[7];
    const float* bn1g  = (const float*)d_in[8];
    const float* bn1b  = (const float*)d_in[9];
    const float* Wtcn  = (const float*)d_in[10];
    const float* btcn  = (const float*)d_in[11];
    const float* bn2g  = (const float*)d_in[12];
    const float* bn2b  = (const float*)d_in[13];
    float* out = (float*)d_out;

    edge_decode_kernel<<<1, 1024>>>(eraw);
    wt_kernel<<<(64 * 3 * 64 + 255) / 256, 256>>>(Wtcn);
    diag_kernel<<<16 * 512, 64>>>(X, w1, b1, w2, b2);
    fused_kernel<<<16 * 64 * 8, 256>>>(X, Wl, bl, bn1g, bn1b,
                                       btcn, bn2g, bn2b, out);
}